// round 11
// baseline (speedup 1.0000x reference)
#include <cuda_runtime.h>
#include <cuda_bf16.h>
#include <math_constants.h>

#define B_  256
#define S_  128
#define D_  768
#define MASK_ID_ 103
#define NB  296          // persistent grid: 2 CTAs/SM on 148 SMs (all co-resident)

// Scratch (no allocation allowed -> device globals)
__device__ float g_feats[B_ * 2 * D_];   // [att | mask_logits], 256 x 1536
__device__ float g_h[B_ * D_];           // tanh(dense) output, 256 x 768
__device__ float g_sraw[B_ * S_];        // raw scores, 256 x 128
__device__ unsigned int g_count;         // monotonic grid-barrier counter (replay-safe)

__constant__ int c_label_ids[21] = {
    2307, 2204, 3835, 2157, 6581, 2986, 5151, 3893,
    7929, 24791, 8699, 4257, 16021, 6623,
    6659, 2919, 11771, 3532, 11325, 4997, 13135
};

__device__ __forceinline__ float warp_sum(float v) {
    #pragma unroll
    for (int o = 16; o; o >>= 1) v += __shfl_xor_sync(0xffffffffu, v, o);
    return v;
}
__device__ __forceinline__ float warp_max(float v) {
    #pragma unroll
    for (int o = 16; o; o >>= 1) v = fmaxf(v, __shfl_xor_sync(0xffffffffu, v, o));
    return v;
}

#define FMA_F32X2(acc, a, b) \
    asm("fma.rn.f32x2 %0, %1, %2, %0;" : "+l"(acc) : "l"(a), "l"(b))

__device__ __forceinline__ float dot4(float4 a, float4 b, float acc) {
    return fmaf(a.x, b.x, fmaf(a.y, b.y, fmaf(a.z, b.z, fmaf(a.w, b.w, acc))));
}

// Grid-wide barrier: monotonic counter, no reset -> safe across graph replays.
// CG-style cumulativity: syncthreads -> t0 fence+arrive -> spin -> fence -> syncthreads.
__device__ __forceinline__ void grid_barrier() {
    __syncthreads();
    if (threadIdx.x == 0) {
        __threadfence();
        unsigned int my = atomicAdd(&g_count, 1u) + 1u;
        unsigned int target = ((my + NB - 1u) / NB) * NB;
        while (*((volatile unsigned int*)&g_count) < target) __nanosleep(64);
        __threadfence();
    }
    __syncthreads();
}

#define BK 32
#define KDIM 1536
#define NDIM 768

struct SmemP1 { float ml[D_]; int mpos; };
struct SmemP2 { float sc[S_]; float red[2]; };
struct SmemP3 { unsigned long long As2u[BK * 17]; unsigned long long Bsdu[BK * 49]; };
struct SmemP4 { float hs[D_]; float probs[21]; };

// ---------------------------------------------------------------------------
// ONE persistent kernel, 4 phases separated by grid barriers.
// ---------------------------------------------------------------------------
__global__ __launch_bounds__(256, 2) void fused_all(
    const float* __restrict__ bert,
    const int*   __restrict__ input_ids,
    const int*   __restrict__ length,
    const float* __restrict__ senti_w,
    const float* __restrict__ senti_b,
    const float* __restrict__ dense_w,
    const float* __restrict__ dense_b,
    const float* __restrict__ dec_w,
    const float* __restrict__ dec_b,
    const float* __restrict__ w0,
    const float* __restrict__ w1,
    const float* __restrict__ w2,
    float*       __restrict__ d_out,
    float*       __restrict__ feats,
    float*       __restrict__ hbuf,
    float*       __restrict__ sraw)
{
    __shared__ union { SmemP1 p1; SmemP2 p2; SmemP3 p3; SmemP4 p4; } sm;

    const int tid  = threadIdx.x;
    const int warp = tid >> 5;
    const int lane = tid & 31;

    // ============ Phase 1: scores_raw = bert . mask_logits =================
    // item = (b, chunk of 16 rows): 256*8 = 2048 items.
    // Each warp: 2 rows, 12 independent LDG.128 in flight (128-reg budget).
    for (int it = blockIdx.x; it < B_ * 8; it += NB) {
        const int b     = it >> 3;
        const int chunk = it & 7;
        const float* base = bert + (size_t)b * (S_ * D_);

        __syncthreads();                       // protect smem reuse
        if (tid == 0) sm.p1.mpos = 0x7fffffff;
        __syncthreads();
        if (tid < S_ && input_ids[b * S_ + tid] == MASK_ID_)
            atomicMin(&sm.p1.mpos, tid);
        __syncthreads();
        const int mp = sm.p1.mpos;

        float4* ml4 = (float4*)sm.p1.ml;
        if (tid < 192) {
            float4 v = ((const float4*)(base + (size_t)mp * D_))[tid];
            ml4[tid] = v;
            if (chunk == 0)
                ((float4*)(feats + (size_t)b * (2 * D_) + D_))[tid] = v;
        }
        __syncthreads();

        const int sA = chunk * 16 + warp;
        const int sB = sA + 8;
        const float4* rA = (const float4*)(base + (size_t)sA * D_);
        const float4* rB = (const float4*)(base + (size_t)sB * D_);

        float4 v0 = rA[lane];       float4 u0 = rB[lane];
        float4 v1 = rA[lane + 32];  float4 u1 = rB[lane + 32];
        float4 v2 = rA[lane + 64];  float4 u2 = rB[lane + 64];
        float4 v3 = rA[lane + 96];  float4 u3 = rB[lane + 96];
        float4 v4 = rA[lane + 128]; float4 u4 = rB[lane + 128];
        float4 v5 = rA[lane + 160]; float4 u5 = rB[lane + 160];

        float a = 0.f, c = 0.f;
        float4 m;
        m = ml4[lane];       a = dot4(v0, m, a); c = dot4(u0, m, c);
        m = ml4[lane + 32];  a = dot4(v1, m, a); c = dot4(u1, m, c);
        m = ml4[lane + 64];  a = dot4(v2, m, a); c = dot4(u2, m, c);
        m = ml4[lane + 96];  a = dot4(v3, m, a); c = dot4(u3, m, c);
        m = ml4[lane + 128]; a = dot4(v4, m, a); c = dot4(u4, m, c);
        m = ml4[lane + 160]; a = dot4(v5, m, a); c = dot4(u5, m, c);
        a = warp_sum(a); c = warp_sum(c);
        if (lane == 0) {
            sraw[b * S_ + sA] = a;
            sraw[b * S_ + sB] = c;
        }
    }

    grid_barrier();

    // ============ Phase 2: softmax + att; feats[b][0:D] = att ==============
    // item = (b, d-chunk of 256): 256*3 = 768 items. bert re-read hits L2.
    for (int it = blockIdx.x; it < B_ * 3; it += NB) {
        const int b  = it / 3;
        const int d0 = (it - b * 3) * 256;

        __syncthreads();                       // protect sc reuse
        if (tid < S_) sm.p2.sc[tid] = __ldcg(sraw + b * S_ + tid);
        __syncthreads();

        const int L = length[b];
        if (warp == 0) {
            float mx = -CUDART_INF_F;
            #pragma unroll
            for (int i = 0; i < 4; i++) {
                int s = lane + 32 * i;
                if (s >= 3 && s < 3 + L) mx = fmaxf(mx, sm.p2.sc[s]);
            }
            mx = warp_max(mx);
            float sum = 0.f;
            #pragma unroll
            for (int i = 0; i < 4; i++) {
                int s = lane + 32 * i;
                if (s >= 3 && s < 3 + L) sum += __expf(sm.p2.sc[s] - mx);
            }
            sum = warp_sum(sum);
            if (lane == 0) { sm.p2.red[0] = mx; sm.p2.red[1] = sum; }
        }
        __syncthreads();
        {
            const float mx  = sm.p2.red[0];
            const float inv = 1.0f / sm.p2.red[1];
            if (tid < S_) {
                bool v = (tid >= 3) && (tid < 3 + L);
                sm.p2.sc[tid] = v ? __expf(sm.p2.sc[tid] - mx) * inv : 0.f;
            }
        }
        __syncthreads();

        const float* col = bert + (size_t)b * (S_ * D_) + d0 + tid;
        float a0 = 0.f, a1 = 0.f, a2 = 0.f, a3 = 0.f;
        #pragma unroll 1
        for (int s0 = 0; s0 < S_; s0 += 16) {
            float x0  = col[(size_t)(s0 +  0) * D_];
            float x1  = col[(size_t)(s0 +  1) * D_];
            float x2  = col[(size_t)(s0 +  2) * D_];
            float x3  = col[(size_t)(s0 +  3) * D_];
            float x4  = col[(size_t)(s0 +  4) * D_];
            float x5  = col[(size_t)(s0 +  5) * D_];
            float x6  = col[(size_t)(s0 +  6) * D_];
            float x7  = col[(size_t)(s0 +  7) * D_];
            float x8  = col[(size_t)(s0 +  8) * D_];
            float x9  = col[(size_t)(s0 +  9) * D_];
            float x10 = col[(size_t)(s0 + 10) * D_];
            float x11 = col[(size_t)(s0 + 11) * D_];
            float x12 = col[(size_t)(s0 + 12) * D_];
            float x13 = col[(size_t)(s0 + 13) * D_];
            float x14 = col[(size_t)(s0 + 14) * D_];
            float x15 = col[(size_t)(s0 + 15) * D_];
            a0 = fmaf(sm.p2.sc[s0 +  0], x0,  a0);  a1 = fmaf(sm.p2.sc[s0 +  1], x1,  a1);
            a2 = fmaf(sm.p2.sc[s0 +  2], x2,  a2);  a3 = fmaf(sm.p2.sc[s0 +  3], x3,  a3);
            a0 = fmaf(sm.p2.sc[s0 +  4], x4,  a0);  a1 = fmaf(sm.p2.sc[s0 +  5], x5,  a1);
            a2 = fmaf(sm.p2.sc[s0 +  6], x6,  a2);  a3 = fmaf(sm.p2.sc[s0 +  7], x7,  a3);
            a0 = fmaf(sm.p2.sc[s0 +  8], x8,  a0);  a1 = fmaf(sm.p2.sc[s0 +  9], x9,  a1);
            a2 = fmaf(sm.p2.sc[s0 + 10], x10, a2);  a3 = fmaf(sm.p2.sc[s0 + 11], x11, a3);
            a0 = fmaf(sm.p2.sc[s0 + 12], x12, a0);  a1 = fmaf(sm.p2.sc[s0 + 13], x13, a1);
            a2 = fmaf(sm.p2.sc[s0 + 14], x14, a2);  a3 = fmaf(sm.p2.sc[s0 + 15], x15, a3);
        }
        feats[(size_t)b * (2 * D_) + d0 + tid] = (a0 + a1) + (a2 + a3);
    }

    grid_barrier();

    // ============ Phase 3: h = tanh(feats @ dense_w^T + b), f32x2 ==========
    // 128 tiles (BM=32 x BN=48); each CTA does at most one.
    for (int it = blockIdx.x; it < 128; it += NB) {
        const int m0 = (it & 7) * 32;
        const int n0 = (it >> 3) * 48;
        const int tx = tid & 15;
        const int ty = tid >> 4;
        float* Asf = (float*)sm.p3.As2u;

        unsigned long long acc0 = 0ull, acc1 = 0ull, acc2 = 0ull;

        for (int k0 = 0; k0 < KDIM; k0 += BK) {
            {
                int r = tid >> 3, c = tid & 7;
                float4 v = __ldcg((const float4*)(feats + (size_t)(m0 + r) * KDIM + k0 + c * 4));
                Asf[(c * 4 + 0) * 34 + r] = v.x;
                Asf[(c * 4 + 1) * 34 + r] = v.y;
                Asf[(c * 4 + 2) * 34 + r] = v.z;
                Asf[(c * 4 + 3) * 34 + r] = v.w;
            }
            {
                int n = tid >> 3, c = tid & 7;
                float4 v = *(const float4*)(dense_w + (size_t)(n0 + n) * KDIM + k0 + c * 4);
                ((float2*)sm.p3.Bsdu)[(c * 4 + 0) * 49 + n] = make_float2(v.x, v.x);
                ((float2*)sm.p3.Bsdu)[(c * 4 + 1) * 49 + n] = make_float2(v.y, v.y);
                ((float2*)sm.p3.Bsdu)[(c * 4 + 2) * 49 + n] = make_float2(v.z, v.z);
                ((float2*)sm.p3.Bsdu)[(c * 4 + 3) * 49 + n] = make_float2(v.w, v.w);
                if (tid < 128) {
                    int idx = tid + 256;
                    n = idx >> 3; c = idx & 7;
                    float4 w = *(const float4*)(dense_w + (size_t)(n0 + n) * KDIM + k0 + c * 4);
                    ((float2*)sm.p3.Bsdu)[(c * 4 + 0) * 49 + n] = make_float2(w.x, w.x);
                    ((float2*)sm.p3.Bsdu)[(c * 4 + 1) * 49 + n] = make_float2(w.y, w.y);
                    ((float2*)sm.p3.Bsdu)[(c * 4 + 2) * 49 + n] = make_float2(w.z, w.z);
                    ((float2*)sm.p3.Bsdu)[(c * 4 + 3) * 49 + n] = make_float2(w.w, w.w);
                }
            }
            __syncthreads();

            #pragma unroll
            for (int k = 0; k < BK; k++) {
                unsigned long long a2 = sm.p3.As2u[k * 17 + ty];
                unsigned long long b0 = sm.p3.Bsdu[k * 49 + tx * 3 + 0];
                unsigned long long b1 = sm.p3.Bsdu[k * 49 + tx * 3 + 1];
                unsigned long long b2 = sm.p3.Bsdu[k * 49 + tx * 3 + 2];
                FMA_F32X2(acc0, a2, b0);
                FMA_F32X2(acc1, a2, b1);
                FMA_F32X2(acc2, a2, b2);
            }
            __syncthreads();
        }

        unsigned long long accs[3] = {acc0, acc1, acc2};
        #pragma unroll
        for (int j = 0; j < 3; j++) {
            unsigned int lo, hi;
            asm("mov.b64 {%0, %1}, %2;" : "=r"(lo), "=r"(hi) : "l"(accs[j]));
            int n = n0 + tx * 3 + j;
            float bv = dense_b[n];
            hbuf[(size_t)(m0 + ty * 2 + 0) * NDIM + n] = tanhf(__uint_as_float(lo) + bv);
            hbuf[(size_t)(m0 + ty * 2 + 1) * NDIM + n] = tanhf(__uint_as_float(hi) + bv);
        }
    }

    grid_barrier();

    // ============ Phase 4: label probs + category + head GEMMs =============
    for (int it = blockIdx.x; it < B_; it += NB) {
        const int b = it;
        if (tid < 192)
            ((float4*)sm.p4.hs)[tid] = __ldcg((const float4*)(hbuf + (size_t)b * D_) + tid);
        __syncthreads();

        const float4* h4 = (const float4*)sm.p4.hs;
        #pragma unroll
        for (int r = 0; r < 3; r++) {
            const int idx = warp + r * 8;
            if (idx < 21) {
                const int id = c_label_ids[idx];
                const float4* r4 = (const float4*)(dec_w + (size_t)id * D_);
                float4 v0 = r4[lane];
                float4 v1 = r4[lane + 32];
                float4 v2 = r4[lane + 64];
                float4 v3 = r4[lane + 96];
                float4 v4 = r4[lane + 128];
                float4 v5 = r4[lane + 160];
                float acc = 0.f;
                acc = dot4(v0, h4[lane],       acc);
                acc = dot4(v1, h4[lane + 32],  acc);
                acc = dot4(v2, h4[lane + 64],  acc);
                acc = dot4(v3, h4[lane + 96],  acc);
                acc = dot4(v4, h4[lane + 128], acc);
                acc = dot4(v5, h4[lane + 160], acc);
                acc = warp_sum(acc);
                if (lane == 0) sm.p4.probs[idx] = tanhf(acc + dec_b[id]);
            }
        }

        // category_out: warps 6,7 (idle in round 3's tail) do the two classes
        if (warp >= 6) {
            const int w = warp - 6;
            const float4* p4 = (const float4*)(bert + (size_t)b * (S_ * D_));
            const float4* w4 = (const float4*)(senti_w + w * D_);
            float4 p0 = p4[lane],       q0 = w4[lane];
            float4 p1 = p4[lane + 32],  q1 = w4[lane + 32];
            float4 p2 = p4[lane + 64],  q2 = w4[lane + 64];
            float4 p3 = p4[lane + 96],  q3 = w4[lane + 96];
            float4 p4v = p4[lane + 128], q4 = w4[lane + 128];
            float4 p5 = p4[lane + 160], q5 = w4[lane + 160];
            float c = 0.f;
            c = dot4(p0, q0, c); c = dot4(p1, q1, c); c = dot4(p2, q2, c);
            c = dot4(p3, q3, c); c = dot4(p4v, q4, c); c = dot4(p5, q5, c);
            c = warp_sum(c);
            if (lane == 0) d_out[b * 2 + w] = c + senti_b[w];
        }
        __syncthreads();

        if (tid < 6) {
            const int j = tid >> 1;
            const int i = tid & 1;
            const float* w   = (j == 0) ? w0 : (j == 1) ? w1 : w2;
            const int    off = (j == 0) ? 0  : (j == 1) ? 8  : 14;
            const int    n   = (j == 0) ? 8  : (j == 1) ? 6  : 7;
            float acc = 0.f;
            for (int l = 0; l < n; l++) acc += w[i * n + l] * sm.p4.probs[off + l];
            d_out[512 + b * 6 + i * 3 + j] = acc;
        }
        __syncthreads();
    }
}

// ---------------------------------------------------------------------------
extern "C" void kernel_launch(void* const* d_in, const int* in_sizes, int n_in,
                              void* d_out, int out_size)
{
    const float* bert      = (const float*)d_in[0];
    const int*   input_ids = (const int*)  d_in[1];
    const int*   length    = (const int*)  d_in[2];
    const float* senti_w   = (const float*)d_in[3];
    const float* senti_b   = (const float*)d_in[4];
    const float* dense_w   = (const float*)d_in[5];
    const float* dense_b   = (const float*)d_in[6];
    const float* dec_w     = (const float*)d_in[7];
    const float* dec_b     = (const float*)d_in[8];
    const float* w0        = (const float*)d_in[9];
    const float* w1        = (const float*)d_in[10];
    const float* w2        = (const float*)d_in[11];
    float* out = (float*)d_out;

    float* feats; cudaGetSymbolAddress((void**)&feats, g_feats);
    float* hbuf;  cudaGetSymbolAddress((void**)&hbuf,  g_h);
    float* sraw;  cudaGetSymbolAddress((void**)&sraw,  g_sraw);

    fused_all<<<NB, 256>>>(bert, input_ids, length, senti_w, senti_b,
                           dense_w, dense_b, dec_w, dec_b, w0, w1, w2,
                           out, feats, hbuf, sraw);
}